// round 2
// baseline (speedup 1.0000x reference)
#include <cuda_runtime.h>
#include <cuda_bf16.h>
#include <math.h>

// ----------------------------------------------------------------------------
// Problem constants
// ----------------------------------------------------------------------------
#define BATCH  2
#define SEQ    2048
#define DIM    1024
#define HEADS  16
#define DHEAD  64
#define INNER  1024
#define ROWS   (BATCH * SEQ)        // 4096
#define ATT_SCALE 0.125f            // 64^-0.5

// Scratch (device globals — no allocation allowed in kernel_launch)
__device__ float g_xn  [ROWS * DIM];        // layernormed x
__device__ float g_q   [ROWS * INNER];      // q projection
__device__ float g_kv  [ROWS * 2 * INNER];  // k|v projection
__device__ float g_attn[ROWS * INNER];      // attention output

// ----------------------------------------------------------------------------
// LayerNorm: one block per row of 1024, 256 threads, float4 per thread
// ----------------------------------------------------------------------------
__global__ void ln_kernel(const float* __restrict__ x,
                          const float* __restrict__ gamma,
                          const float* __restrict__ beta,
                          float* __restrict__ xn) {
    int row = blockIdx.x;
    int t   = threadIdx.x;            // 256
    const float* xr = x + (size_t)row * DIM;

    float4 v = *(const float4*)&xr[t * 4];
    float s  = v.x + v.y + v.z + v.w;
    float s2 = v.x*v.x + v.y*v.y + v.z*v.z + v.w*v.w;

    #pragma unroll
    for (int o = 16; o; o >>= 1) {
        s  += __shfl_xor_sync(0xffffffffu, s,  o);
        s2 += __shfl_xor_sync(0xffffffffu, s2, o);
    }
    __shared__ float sh1[8], sh2[8];
    int w = t >> 5, l = t & 31;
    if (l == 0) { sh1[w] = s; sh2[w] = s2; }
    __syncthreads();
    float ts = 0.f, ts2 = 0.f;
    #pragma unroll
    for (int i = 0; i < 8; i++) { ts += sh1[i]; ts2 += sh2[i]; }

    float mean = ts * (1.0f / DIM);
    float var  = ts2 * (1.0f / DIM) - mean * mean;
    float rstd = rsqrtf(var + 1e-5f);

    float4 g = *(const float4*)&gamma[t * 4];
    float4 bb = *(const float4*)&beta[t * 4];
    float4 o;
    o.x = (v.x - mean) * rstd * g.x + bb.x;
    o.y = (v.y - mean) * rstd * g.y + bb.y;
    o.z = (v.z - mean) * rstd * g.z + bb.z;
    o.w = (v.w - mean) * rstd * g.w + bb.w;
    *(float4*)&xn[(size_t)row * DIM + t * 4] = o;
}

// ----------------------------------------------------------------------------
// SGEMM: C[M,N] = A[M,K] @ B[K,N] (+ bias[N]); 128x128x8 tiles, 256 thr, 8x8/thr
// ----------------------------------------------------------------------------
__global__ __launch_bounds__(256) void sgemm_kernel(
    const float* __restrict__ A, const float* __restrict__ B,
    float* __restrict__ C, const float* __restrict__ bias,
    int M, int N, int K) {
    __shared__ float As[8][128];
    __shared__ float Bs[8][128];

    int t  = threadIdx.x;
    int bm = blockIdx.y * 128;
    int bn = blockIdx.x * 128;

    int arow = t >> 1, acol = (t & 1) * 4;   // A tile 128x8, float4 each
    int brow = t >> 5, bcol = (t & 31) * 4;  // B tile 8x128, float4 each
    int ty = t >> 4, tx = t & 15;

    float acc[8][8];
    #pragma unroll
    for (int i = 0; i < 8; i++)
        #pragma unroll
        for (int j = 0; j < 8; j++) acc[i][j] = 0.f;

    for (int k0 = 0; k0 < K; k0 += 8) {
        float4 av = *(const float4*)&A[(size_t)(bm + arow) * K + k0 + acol];
        As[acol + 0][arow] = av.x;
        As[acol + 1][arow] = av.y;
        As[acol + 2][arow] = av.z;
        As[acol + 3][arow] = av.w;
        float4 bv = *(const float4*)&B[(size_t)(k0 + brow) * N + bn + bcol];
        *(float4*)&Bs[brow][bcol] = bv;
        __syncthreads();

        #pragma unroll
        for (int kk = 0; kk < 8; kk++) {
            float a[8], b[8];
            #pragma unroll
            for (int i = 0; i < 8; i++) a[i] = As[kk][ty * 8 + i];
            #pragma unroll
            for (int j = 0; j < 8; j++) b[j] = Bs[kk][tx * 8 + j];
            #pragma unroll
            for (int i = 0; i < 8; i++)
                #pragma unroll
                for (int j = 0; j < 8; j++) acc[i][j] += a[i] * b[j];
        }
        __syncthreads();
    }

    #pragma unroll
    for (int i = 0; i < 8; i++) {
        size_t row = bm + ty * 8 + i;
        #pragma unroll
        for (int j = 0; j < 8; j += 4) {
            int col = bn + tx * 8 + j;
            float4 v = make_float4(acc[i][j], acc[i][j+1], acc[i][j+2], acc[i][j+3]);
            if (bias) {
                v.x += bias[col];   v.y += bias[col+1];
                v.z += bias[col+2]; v.w += bias[col+3];
            }
            *(float4*)&C[row * N + col] = v;
        }
    }
}

// ----------------------------------------------------------------------------
// Flash attention v2: 128x64 tiles, 128 threads, 8x8 microtile per thread.
//   Qt: d-major [64][132]   (q rows scaled by ATT_SCALE at load)
//   Kt: d-major [64][68]
//   Vs: key-major [64][68]
//   Ps: [128][65], column swizzle pcol = (col + (row>>3)) & 63  (conflict-free)
// Thread map: ty = t>>3 in [0,16) owns rows ty*8..+7; tx = t&7 owns cols tx*8..+7.
// Softmax reductions across tx live in lane bits 0..2 -> shfl_xor 1,2,4.
// ----------------------------------------------------------------------------
#define QT_STR 132
#define KT_STR 68
#define VS_STR 68
#define PS_STR 65
#define ATTN_SMEM_FLOATS (64*QT_STR + 64*KT_STR + 64*VS_STR + 128*PS_STR)

__global__ __launch_bounds__(128) void attn_kernel(
    const float* __restrict__ q, const float* __restrict__ kv,
    float* __restrict__ o) {
    extern __shared__ float sm[];
    float* Qt = sm;                       // [64][QT_STR]
    float* Kt = Qt + 64 * QT_STR;         // [64][KT_STR]
    float* Vs = Kt + 64 * KT_STR;         // [64][VS_STR]
    float* Ps = Vs + 64 * VS_STR;         // [128][PS_STR]

    int bh = blockIdx.y;
    int b  = bh >> 4, h = bh & 15;
    int q0 = blockIdx.x * 128;
    int t  = threadIdx.x;
    int ty = t >> 3, tx = t & 7;

    // Load Q tile transposed (d-major), scale folded in. Thread t = row.
    {
        const float* qrow = q + ((size_t)(b * SEQ + q0 + t)) * INNER + h * DHEAD;
        #pragma unroll
        for (int d4 = 0; d4 < 16; d4++) {
            float4 v = *(const float4*)(qrow + d4 * 4);
            Qt[(d4*4 + 0) * QT_STR + t] = v.x * ATT_SCALE;
            Qt[(d4*4 + 1) * QT_STR + t] = v.y * ATT_SCALE;
            Qt[(d4*4 + 2) * QT_STR + t] = v.z * ATT_SCALE;
            Qt[(d4*4 + 3) * QT_STR + t] = v.w * ATT_SCALE;
        }
    }

    float m_i[8], l_i[8], acc[8][8];
    #pragma unroll
    for (int i = 0; i < 8; i++) {
        m_i[i] = -1e30f; l_i[i] = 0.f;
        #pragma unroll
        for (int c = 0; c < 8; c++) acc[i][c] = 0.f;
    }

    for (int j0 = 0; j0 < SEQ; j0 += 64) {
        __syncthreads();   // previous tile's Kt/Vs/Ps reads complete
        // Load K (transposed) and V: 64 rows; thread handles row r = t&63,
        // d4 range [hseg, hseg+8).
        {
            int r = t & 63, hseg = (t >> 6) * 8;
            size_t base = ((size_t)(b * SEQ + j0 + r)) * (2 * INNER) + h * DHEAD;
            #pragma unroll
            for (int d4 = 0; d4 < 8; d4++) {
                int d = (hseg + d4) * 4;
                float4 kk = *(const float4*)&kv[base + d];
                Kt[(d + 0) * KT_STR + r] = kk.x;
                Kt[(d + 1) * KT_STR + r] = kk.y;
                Kt[(d + 2) * KT_STR + r] = kk.z;
                Kt[(d + 3) * KT_STR + r] = kk.w;
                float4 vv = *(const float4*)&kv[base + INNER + d];
                *(float4*)&Vs[r * VS_STR + d] = vv;
            }
        }
        __syncthreads();

        // S = (Q*scale) K^T : 8x8 per thread
        float s[8][8];
        #pragma unroll
        for (int i = 0; i < 8; i++)
            #pragma unroll
            for (int j = 0; j < 8; j++) s[i][j] = 0.f;

        #pragma unroll 4
        for (int d = 0; d < 64; d++) {
            float4 a0 = *(const float4*)&Qt[d * QT_STR + ty * 8];
            float4 a1 = *(const float4*)&Qt[d * QT_STR + ty * 8 + 4];
            float4 b0 = *(const float4*)&Kt[d * KT_STR + tx * 8];
            float4 b1 = *(const float4*)&Kt[d * KT_STR + tx * 8 + 4];
            float a[8] = {a0.x,a0.y,a0.z,a0.w,a1.x,a1.y,a1.z,a1.w};
            float bb[8] = {b0.x,b0.y,b0.z,b0.w,b1.x,b1.y,b1.z,b1.w};
            #pragma unroll
            for (int i = 0; i < 8; i++)
                #pragma unroll
                for (int j = 0; j < 8; j++) s[i][j] += a[i] * bb[j];
        }

        // Online softmax per row; write P to swizzled smem.
        #pragma unroll
        for (int i = 0; i < 8; i++) {
            float mx = s[i][0];
            #pragma unroll
            for (int j = 1; j < 8; j++) mx = fmaxf(mx, s[i][j]);
            #pragma unroll
            for (int off = 1; off < 8; off <<= 1)
                mx = fmaxf(mx, __shfl_xor_sync(0xffffffffu, mx, off));
            float mn = fmaxf(m_i[i], mx);
            float alpha = __expf(m_i[i] - mn);
            m_i[i] = mn;
            float rs = 0.f;
            #pragma unroll
            for (int j = 0; j < 8; j++) {
                s[i][j] = __expf(s[i][j] - mn);
                rs += s[i][j];
            }
            #pragma unroll
            for (int off = 1; off < 8; off <<= 1)
                rs += __shfl_xor_sync(0xffffffffu, rs, off);
            l_i[i] = l_i[i] * alpha + rs;
            #pragma unroll
            for (int c = 0; c < 8; c++) acc[i][c] *= alpha;
            int row = ty * 8 + i;
            #pragma unroll
            for (int j = 0; j < 8; j++) {
                int pcol = ((tx * 8 + j) + ty) & 63;
                Ps[row * PS_STR + pcol] = s[i][j];
            }
        }
        __syncthreads();

        // acc += P @ V  (thread owns rows ty*8..+7, d-cols tx*8..+7)
        #pragma unroll 2
        for (int j = 0; j < 64; j++) {
            float4 v0 = *(const float4*)&Vs[j * VS_STR + tx * 8];
            float4 v1 = *(const float4*)&Vs[j * VS_STR + tx * 8 + 4];
            float vv[8] = {v0.x,v0.y,v0.z,v0.w,v1.x,v1.y,v1.z,v1.w};
            int pcol = (j + ty) & 63;
            float pp[8];
            #pragma unroll
            for (int i = 0; i < 8; i++)
                pp[i] = Ps[(ty * 8 + i) * PS_STR + pcol];
            #pragma unroll
            for (int i = 0; i < 8; i++)
                #pragma unroll
                for (int c = 0; c < 8; c++) acc[i][c] += pp[i] * vv[c];
        }
    }

    // Epilogue: normalize and store
    #pragma unroll
    for (int i = 0; i < 8; i++) {
        float inv = 1.f / l_i[i];
        size_t row = (size_t)(b * SEQ + q0 + ty * 8 + i);
        float* op = o + row * INNER + h * DHEAD + tx * 8;
        float4 o0 = make_float4(acc[i][0]*inv, acc[i][1]*inv, acc[i][2]*inv, acc[i][3]*inv);
        float4 o1 = make_float4(acc[i][4]*inv, acc[i][5]*inv, acc[i][6]*inv, acc[i][7]*inv);
        *(float4*)(op)     = o0;
        *(float4*)(op + 4) = o1;
    }
}

// ----------------------------------------------------------------------------
// Launch
// ----------------------------------------------------------------------------
extern "C" void kernel_launch(void* const* d_in, const int* in_sizes, int n_in,
                              void* d_out, int out_size) {
    const float* x     = (const float*)d_in[0];
    const float* w_q   = (const float*)d_in[1];
    const float* w_kv  = (const float*)d_in[2];
    const float* w_out = (const float*)d_in[3];
    const float* b_out = (const float*)d_in[4];
    const float* gamma = (const float*)d_in[5];
    const float* beta  = (const float*)d_in[6];
    float* out = (float*)d_out;

    void *p_xn, *p_q, *p_kv, *p_attn;
    cudaGetSymbolAddress(&p_xn,   g_xn);
    cudaGetSymbolAddress(&p_q,    g_q);
    cudaGetSymbolAddress(&p_kv,   g_kv);
    cudaGetSymbolAddress(&p_attn, g_attn);
    float* xn   = (float*)p_xn;
    float* qb   = (float*)p_q;
    float* kvb  = (float*)p_kv;
    float* attn = (float*)p_attn;

    const int attn_smem = ATTN_SMEM_FLOATS * (int)sizeof(float);  // 101,888 B
    cudaFuncSetAttribute(attn_kernel,
                         cudaFuncAttributeMaxDynamicSharedMemorySize, attn_smem);

    // 1) LayerNorm
    ln_kernel<<<ROWS, 256>>>(x, gamma, beta, xn);

    // 2) Q and KV projections
    sgemm_kernel<<<dim3(INNER / 128, ROWS / 128), 256>>>(
        xn, w_q, qb, nullptr, ROWS, INNER, DIM);
    sgemm_kernel<<<dim3((2 * INNER) / 128, ROWS / 128), 256>>>(
        xn, w_kv, kvb, nullptr, ROWS, 2 * INNER, DIM);

    // 3) Flash attention (128 q-rows per CTA, 64-key tiles)
    attn_kernel<<<dim3(SEQ / 128, BATCH * HEADS), 128, attn_smem>>>(qb, kvb, attn);

    // 4) Output projection + bias
    sgemm_kernel<<<dim3(DIM / 128, ROWS / 128), 256>>>(
        attn, w_out, out, b_out, ROWS, DIM, DIM);
}

// round 4
// speedup vs baseline: 1.3140x; 1.3140x over previous
#include <cuda_runtime.h>
#include <cuda_bf16.h>
#include <math.h>
#include <stdint.h>

// ----------------------------------------------------------------------------
// Problem constants
// ----------------------------------------------------------------------------
#define BATCH  2
#define SEQ    2048
#define DIM    1024
#define HEADS  16
#define DHEAD  64
#define INNER  1024
#define ROWS   (BATCH * SEQ)        // 4096
#define GK     1024                 // GEMM K (always 1024 here)
#define ATT_SCALE 0.125f

// Scratch (device globals — no allocation allowed in kernel_launch)
__device__ float g_xn   [ROWS * DIM];         // layernormed x (tf32-rounded)
__device__ float g_q    [ROWS * INNER];       // q projection (fp32)
__device__ float g_kv   [ROWS * 2 * INNER];   // k|v projection (fp32)
__device__ float g_attn [ROWS * INNER];       // attention out (tf32-rounded)
__device__ float g_wqT  [INNER * DIM];        // w_q^T  [N,K] tf32
__device__ float g_wkvT [2 * INNER * DIM];    // w_kv^T [N,K] tf32
__device__ float g_woutT[DIM * INNER];        // w_out^T[N,K] tf32

// ----------------------------------------------------------------------------
// Helpers
// ----------------------------------------------------------------------------
__device__ __forceinline__ uint32_t smem_u32(const void* p) {
    uint32_t a;
    asm("{ .reg .u64 t; cvta.to.shared.u64 t, %1; cvt.u32.u64 %0, t; }"
        : "=r"(a) : "l"(p));
    return a;
}
__device__ __forceinline__ float to_tf32(float x) {
    float r;
    asm("cvt.rna.tf32.f32 %0, %1;" : "=f"(r) : "f"(x));
    return r;
}

#define CP_ASYNC16(dst, src) \
    asm volatile("cp.async.cg.shared.global [%0], [%1], 16;" \
                 :: "r"(dst), "l"(src) : "memory")
#define CP_COMMIT() asm volatile("cp.async.commit_group;" ::: "memory")
#define CP_WAIT(n)  asm volatile("cp.async.wait_group %0;" :: "n"(n) : "memory")

// m16n8k8 tf32 mma: D += A*B (row.col), fp32 accum
__device__ __forceinline__ void mma_tf32(float* d, const uint32_t* a,
                                         const uint32_t* b) {
    asm volatile(
        "mma.sync.aligned.m16n8k8.row.col.f32.tf32.tf32.f32 "
        "{%0,%1,%2,%3}, {%4,%5,%6,%7}, {%8,%9}, {%0,%1,%2,%3};"
        : "+f"(d[0]), "+f"(d[1]), "+f"(d[2]), "+f"(d[3])
        : "r"(a[0]), "r"(a[1]), "r"(a[2]), "r"(a[3]), "r"(b[0]), "r"(b[1]));
}

// Swizzled smem fragment read: tile row-major, 32 floats/row,
// float4-column swizzle f4' = f4 ^ (row & 7). Conflict-free for mma frags.
__device__ __forceinline__ uint32_t lds_sw(const float* base, int row, int kf) {
    int idx = row * 32 + ((((kf >> 2) ^ (row & 7)) << 2) | (kf & 3));
    return __float_as_uint(base[idx]);
}

// ----------------------------------------------------------------------------
// LayerNorm (tf32-rounded output)
// ----------------------------------------------------------------------------
__global__ void ln_kernel(const float* __restrict__ x,
                          const float* __restrict__ gamma,
                          const float* __restrict__ beta,
                          float* __restrict__ xn) {
    int row = blockIdx.x;
    int t   = threadIdx.x;
    const float* xr = x + (size_t)row * DIM;

    float4 v = *(const float4*)&xr[t * 4];
    float s  = v.x + v.y + v.z + v.w;
    float s2 = v.x*v.x + v.y*v.y + v.z*v.z + v.w*v.w;
    #pragma unroll
    for (int o = 16; o; o >>= 1) {
        s  += __shfl_xor_sync(0xffffffffu, s,  o);
        s2 += __shfl_xor_sync(0xffffffffu, s2, o);
    }
    __shared__ float sh1[8], sh2[8];
    int w = t >> 5, l = t & 31;
    if (l == 0) { sh1[w] = s; sh2[w] = s2; }
    __syncthreads();
    float ts = 0.f, ts2 = 0.f;
    #pragma unroll
    for (int i = 0; i < 8; i++) { ts += sh1[i]; ts2 += sh2[i]; }

    float mean = ts * (1.0f / DIM);
    float var  = ts2 * (1.0f / DIM) - mean * mean;
    float rstd = rsqrtf(var + 1e-5f);

    float4 g  = *(const float4*)&gamma[t * 4];
    float4 bb = *(const float4*)&beta[t * 4];
    float4 o;
    o.x = to_tf32((v.x - mean) * rstd * g.x + bb.x);
    o.y = to_tf32((v.y - mean) * rstd * g.y + bb.y);
    o.z = to_tf32((v.z - mean) * rstd * g.z + bb.z);
    o.w = to_tf32((v.w - mean) * rstd * g.w + bb.w);
    *(float4*)&xn[(size_t)row * DIM + t * 4] = o;
}

// ----------------------------------------------------------------------------
// Transpose + tf32 round: Wt[n,k] = tf32(W[k,n]).  W is [K, N].
// ----------------------------------------------------------------------------
__global__ void transpose_tf32_kernel(const float* __restrict__ W,
                                      float* __restrict__ Wt, int K, int N) {
    __shared__ float tile[32][33];
    int n0 = blockIdx.x * 32, k0 = blockIdx.y * 32;
    int tx = threadIdx.x, ty = threadIdx.y;
    #pragma unroll
    for (int i = ty; i < 32; i += 8)
        tile[i][tx] = W[(size_t)(k0 + i) * N + n0 + tx];
    __syncthreads();
    #pragma unroll
    for (int i = ty; i < 32; i += 8)
        Wt[(size_t)(n0 + i) * K + k0 + tx] = to_tf32(tile[tx][i]);
}

// ----------------------------------------------------------------------------
// tf32 mma.sync GEMM: C[M,N](+bias) = A[M,1024] @ Bt[N,1024]^T
// 128x128 CTA, 256 threads (8 warps, 4m x 2n, warp tile 32x64).
// K-chunk 32, 2-stage cp.async pipeline, XOR-swizzled smem.
// ----------------------------------------------------------------------------
#define GEMM_SMEM_FLOATS (4 * 4096)   // A0 A1 B0 B1, each 128x32
#define CHUNKS (GK / 32)

__global__ __launch_bounds__(256)
void gemm_mma_kernel(const float* __restrict__ A,
                     const float* __restrict__ Bt,
                     float* __restrict__ C,
                     const float* __restrict__ bias,
                     int N) {
    extern __shared__ float smg[];
    float* sA[2] = { smg,          smg + 4096 };
    float* sB[2] = { smg + 8192,   smg + 12288 };
    uint32_t uA[2] = { smem_u32(sA[0]), smem_u32(sA[1]) };
    uint32_t uB[2] = { smem_u32(sB[0]), smem_u32(sB[1]) };

    int t    = threadIdx.x;
    int lane = t & 31;
    int wid  = t >> 5;
    int wm   = wid >> 1;          // 0..3  (32-row band)
    int wn   = wid & 1;           // 0..1  (64-col band)
    int gid  = lane >> 2;         // 0..7
    int tig  = lane & 3;          // 0..3
    int bm   = blockIdx.y * 128;
    int bn   = blockIdx.x * 128;

    const float* Ag = A  + (size_t)bm * GK;
    const float* Bg = Bt + (size_t)bn * GK;

    float acc[2][8][4];
    #pragma unroll
    for (int mt = 0; mt < 2; mt++)
        #pragma unroll
        for (int nt = 0; nt < 8; nt++)
            #pragma unroll
            for (int i = 0; i < 4; i++) acc[mt][nt][i] = 0.f;

    // chunk loader: 4 cp.async for A + 4 for B per thread
    auto load_chunk = [&](int c, int s) {
        int k0 = c * 32;
        #pragma unroll
        for (int i = 0; i < 4; ++i) {
            int idx = t + i * 256;            // 0..1023
            int row = idx >> 3, q = idx & 7;
            uint32_t d = uA[s] + (uint32_t)((row * 32 + ((q ^ (row & 7)) << 2)) * 4);
            CP_ASYNC16(d, Ag + (size_t)row * GK + k0 + q * 4);
        }
        #pragma unroll
        for (int i = 0; i < 4; ++i) {
            int idx = t + i * 256;
            int row = idx >> 3, q = idx & 7;
            uint32_t d = uB[s] + (uint32_t)((row * 32 + ((q ^ (row & 7)) << 2)) * 4);
            CP_ASYNC16(d, Bg + (size_t)row * GK + k0 + q * 4);
        }
        CP_COMMIT();
    };

    load_chunk(0, 0);
    load_chunk(1, 1);

    for (int c = 0; c < CHUNKS; ++c) {
        int s = c & 1;
        if (c == CHUNKS - 1) { CP_WAIT(0); } else { CP_WAIT(1); }
        __syncthreads();

        const float* a_s = sA[s];
        const float* b_s = sB[s];
        #pragma unroll
        for (int g = 0; g < 4; ++g) {
            uint32_t af[2][4];
            #pragma unroll
            for (int mt = 0; mt < 2; mt++) {
                int r = wm * 32 + mt * 16 + gid;
                af[mt][0] = lds_sw(a_s, r,     g * 8 + tig);
                af[mt][1] = lds_sw(a_s, r + 8, g * 8 + tig);
                af[mt][2] = lds_sw(a_s, r,     g * 8 + tig + 4);
                af[mt][3] = lds_sw(a_s, r + 8, g * 8 + tig + 4);
            }
            uint32_t bf[8][2];
            #pragma unroll
            for (int nt = 0; nt < 8; nt++) {
                int n = wn * 64 + nt * 8 + gid;
                bf[nt][0] = lds_sw(b_s, n, g * 8 + tig);
                bf[nt][1] = lds_sw(b_s, n, g * 8 + tig + 4);
            }
            #pragma unroll
            for (int mt = 0; mt < 2; mt++)
                #pragma unroll
                for (int nt = 0; nt < 8; nt++)
                    mma_tf32(acc[mt][nt], af[mt], bf[nt]);
        }
        __syncthreads();
        if (c + 2 < CHUNKS) load_chunk(c + 2, s);
    }

    // Epilogue
    #pragma unroll
    for (int mt = 0; mt < 2; mt++) {
        int r0 = bm + wm * 32 + mt * 16 + gid;
        #pragma unroll
        for (int nt = 0; nt < 8; nt++) {
            int cc = bn + wn * 64 + nt * 8 + tig * 2;
            float b0 = bias ? bias[cc]     : 0.f;
            float b1 = bias ? bias[cc + 1] : 0.f;
            *(float2*)&C[(size_t)r0 * N + cc] =
                make_float2(acc[mt][nt][0] + b0, acc[mt][nt][1] + b1);
            *(float2*)&C[(size_t)(r0 + 8) * N + cc] =
                make_float2(acc[mt][nt][2] + b0, acc[mt][nt][3] + b1);
        }
    }
}

// ----------------------------------------------------------------------------
// Flash attention (fp32 SIMT; epilogue rounds to tf32 for w_out GEMM)
// ----------------------------------------------------------------------------
#define QT_STR 132
#define KT_STR 68
#define VS_STR 68
#define PS_STR 65
#define ATTN_SMEM_FLOATS (64*QT_STR + 64*KT_STR + 64*VS_STR + 128*PS_STR)

__global__ __launch_bounds__(128) void attn_kernel(
    const float* __restrict__ q, const float* __restrict__ kv,
    float* __restrict__ o) {
    extern __shared__ float smf[];
    float* Qt = smf;
    float* Kt = Qt + 64 * QT_STR;
    float* Vs = Kt + 64 * KT_STR;
    float* Ps = Vs + 64 * VS_STR;

    int bh = blockIdx.y;
    int b  = bh >> 4, h = bh & 15;
    int q0 = blockIdx.x * 128;
    int t  = threadIdx.x;
    int ty = t >> 3, tx = t & 7;

    {
        const float* qrow = q + ((size_t)(b * SEQ + q0 + t)) * INNER + h * DHEAD;
        #pragma unroll
        for (int d4 = 0; d4 < 16; d4++) {
            float4 v = *(const float4*)(qrow + d4 * 4);
            Qt[(d4*4 + 0) * QT_STR + t] = v.x * ATT_SCALE;
            Qt[(d4*4 + 1) * QT_STR + t] = v.y * ATT_SCALE;
            Qt[(d4*4 + 2) * QT_STR + t] = v.z * ATT_SCALE;
            Qt[(d4*4 + 3) * QT_STR + t] = v.w * ATT_SCALE;
        }
    }

    float m_i[8], l_i[8], acc[8][8];
    #pragma unroll
    for (int i = 0; i < 8; i++) {
        m_i[i] = -1e30f; l_i[i] = 0.f;
        #pragma unroll
        for (int c = 0; c < 8; c++) acc[i][c] = 0.f;
    }

    for (int j0 = 0; j0 < SEQ; j0 += 64) {
        __syncthreads();
        {
            int r = t & 63, hseg = (t >> 6) * 8;
            size_t bse = ((size_t)(b * SEQ + j0 + r)) * (2 * INNER) + h * DHEAD;
            #pragma unroll
            for (int d4 = 0; d4 < 8; d4++) {
                int d = (hseg + d4) * 4;
                float4 kk = *(const float4*)&kv[bse + d];
                Kt[(d + 0) * KT_STR + r] = kk.x;
                Kt[(d + 1) * KT_STR + r] = kk.y;
                Kt[(d + 2) * KT_STR + r] = kk.z;
                Kt[(d + 3) * KT_STR + r] = kk.w;
                float4 vv = *(const float4*)&kv[bse + INNER + d];
                *(float4*)&Vs[r * VS_STR + d] = vv;
            }
        }
        __syncthreads();

        float s[8][8];
        #pragma unroll
        for (int i = 0; i < 8; i++)
            #pragma unroll
            for (int j = 0; j < 8; j++) s[i][j] = 0.f;

        #pragma unroll 4
        for (int d = 0; d < 64; d++) {
            float4 a0 = *(const float4*)&Qt[d * QT_STR + ty * 8];
            float4 a1 = *(const float4*)&Qt[d * QT_STR + ty * 8 + 4];
            float4 b0 = *(const float4*)&Kt[d * KT_STR + tx * 8];
            float4 b1 = *(const float4*)&Kt[d * KT_STR + tx * 8 + 4];
            float a[8] = {a0.x,a0.y,a0.z,a0.w,a1.x,a1.y,a1.z,a1.w};
            float bb[8] = {b0.x,b0.y,b0.z,b0.w,b1.x,b1.y,b1.z,b1.w};
            #pragma unroll
            for (int i = 0; i < 8; i++)
                #pragma unroll
                for (int j = 0; j < 8; j++) s[i][j] += a[i] * bb[j];
        }

        #pragma unroll
        for (int i = 0; i < 8; i++) {
            float mx = s[i][0];
            #pragma unroll
            for (int j = 1; j < 8; j++) mx = fmaxf(mx, s[i][j]);
            #pragma unroll
            for (int off = 1; off < 8; off <<= 1)
                mx = fmaxf(mx, __shfl_xor_sync(0xffffffffu, mx, off));
            float mn = fmaxf(m_i[i], mx);
            float alpha = __expf(m_i[i] - mn);
            m_i[i] = mn;
            float rs = 0.f;
            #pragma unroll
            for (int j = 0; j < 8; j++) {
                s[i][j] = __expf(s[i][j] - mn);
                rs += s[i][j];
            }
            #pragma unroll
            for (int off = 1; off < 8; off <<= 1)
                rs += __shfl_xor_sync(0xffffffffu, rs, off);
            l_i[i] = l_i[i] * alpha + rs;
            #pragma unroll
            for (int c = 0; c < 8; c++) acc[i][c] *= alpha;
            int row = ty * 8 + i;
            #pragma unroll
            for (int j = 0; j < 8; j++) {
                int pcol = ((tx * 8 + j) + ty) & 63;
                Ps[row * PS_STR + pcol] = s[i][j];
            }
        }
        __syncthreads();

        #pragma unroll 2
        for (int j = 0; j < 64; j++) {
            float4 v0 = *(const float4*)&Vs[j * VS_STR + tx * 8];
            float4 v1 = *(const float4*)&Vs[j * VS_STR + tx * 8 + 4];
            float vv[8] = {v0.x,v0.y,v0.z,v0.w,v1.x,v1.y,v1.z,v1.w};
            int pcol = (j + ty) & 63;
            float pp[8];
            #pragma unroll
            for (int i = 0; i < 8; i++)
                pp[i] = Ps[(ty * 8 + i) * PS_STR + pcol];
            #pragma unroll
            for (int i = 0; i < 8; i++)
                #pragma unroll
                for (int c = 0; c < 8; c++) acc[i][c] += pp[i] * vv[c];
        }
    }

    #pragma unroll
    for (int i = 0; i < 8; i++) {
        float inv = 1.f / l_i[i];
        size_t row = (size_t)(b * SEQ + q0 + ty * 8 + i);
        float* op = o + row * INNER + h * DHEAD + tx * 8;
        float4 o0 = make_float4(to_tf32(acc[i][0]*inv), to_tf32(acc[i][1]*inv),
                                to_tf32(acc[i][2]*inv), to_tf32(acc[i][3]*inv));
        float4 o1 = make_float4(to_tf32(acc[i][4]*inv), to_tf32(acc[i][5]*inv),
                                to_tf32(acc[i][6]*inv), to_tf32(acc[i][7]*inv));
        *(float4*)(op)     = o0;
        *(float4*)(op + 4) = o1;
    }
}

// ----------------------------------------------------------------------------
// Launch
// ----------------------------------------------------------------------------
extern "C" void kernel_launch(void* const* d_in, const int* in_sizes, int n_in,
                              void* d_out, int out_size) {
    const float* x     = (const float*)d_in[0];
    const float* w_q   = (const float*)d_in[1];
    const float* w_kv  = (const float*)d_in[2];
    const float* w_out = (const float*)d_in[3];
    const float* b_out = (const float*)d_in[4];
    const float* gamma = (const float*)d_in[5];
    const float* beta  = (const float*)d_in[6];
    float* out = (float*)d_out;

    void *p_xn, *p_q, *p_kv, *p_attn, *p_wqT, *p_wkvT, *p_woutT;
    cudaGetSymbolAddress(&p_xn,    g_xn);
    cudaGetSymbolAddress(&p_q,     g_q);
    cudaGetSymbolAddress(&p_kv,    g_kv);
    cudaGetSymbolAddress(&p_attn,  g_attn);
    cudaGetSymbolAddress(&p_wqT,   g_wqT);
    cudaGetSymbolAddress(&p_wkvT,  g_wkvT);
    cudaGetSymbolAddress(&p_woutT, g_woutT);
    float* xn    = (float*)p_xn;
    float* qb    = (float*)p_q;
    float* kvb   = (float*)p_kv;
    float* attn  = (float*)p_attn;
    float* wqT   = (float*)p_wqT;
    float* wkvT  = (float*)p_wkvT;
    float* woutT = (float*)p_woutT;

    const int attn_smem = ATTN_SMEM_FLOATS * (int)sizeof(float);
    const int gemm_smem = GEMM_SMEM_FLOATS * (int)sizeof(float);   // 65536
    cudaFuncSetAttribute(attn_kernel,
                         cudaFuncAttributeMaxDynamicSharedMemorySize, attn_smem);
    cudaFuncSetAttribute(gemm_mma_kernel,
                         cudaFuncAttributeMaxDynamicSharedMemorySize, gemm_smem);

    // 0) Weight transposes (+ tf32 rounding)
    transpose_tf32_kernel<<<dim3(INNER/32,     DIM/32), dim3(32, 8)>>>(w_q,   wqT,   DIM, INNER);
    transpose_tf32_kernel<<<dim3(2*INNER/32,   DIM/32), dim3(32, 8)>>>(w_kv,  wkvT,  DIM, 2*INNER);
    transpose_tf32_kernel<<<dim3(DIM/32,     INNER/32), dim3(32, 8)>>>(w_out, woutT, INNER, DIM);

    // 1) LayerNorm (tf32-rounded output)
    ln_kernel<<<ROWS, 256>>>(x, gamma, beta, xn);

    // 2) Q and KV projections (mma.sync tf32)
    gemm_mma_kernel<<<dim3(INNER/128,   ROWS/128), 256, gemm_smem>>>(
        xn, wqT, qb, nullptr, INNER);
    gemm_mma_kernel<<<dim3(2*INNER/128, ROWS/128), 256, gemm_smem>>>(
        xn, wkvT, kvb, nullptr, 2*INNER);

    // 3) Flash attention (fp32 SIMT)
    attn_kernel<<<dim3(SEQ/128, BATCH*HEADS), 128, attn_smem>>>(qb, kvb, attn);

    // 4) Output projection + bias (mma.sync tf32)
    gemm_mma_kernel<<<dim3(DIM/128, ROWS/128), 256, gemm_smem>>>(
        attn, woutT, out, b_out, DIM);
}

// round 5
// speedup vs baseline: 2.8905x; 2.1998x over previous
#include <cuda_runtime.h>
#include <cuda_bf16.h>
#include <math.h>
#include <stdint.h>

// ----------------------------------------------------------------------------
// Problem constants
// ----------------------------------------------------------------------------
#define BATCH  2
#define SEQ    2048
#define DIM    1024
#define HEADS  16
#define DHEAD  64
#define INNER  1024
#define ROWS   (BATCH * SEQ)        // 4096
#define GK     1024                 // GEMM K (always 1024 here)
#define ATT_SCALE 0.125f

// Scratch (device globals — no allocation allowed in kernel_launch)
__device__ float g_xn   [ROWS * DIM];         // layernormed x (tf32-rounded)
__device__ float g_q    [ROWS * INNER];       // q projection (fp32)
__device__ float g_kv   [ROWS * 2 * INNER];   // k|v projection (fp32)
__device__ float g_attn [ROWS * INNER];       // attention out (tf32-rounded)
__device__ float g_wqT  [INNER * DIM];        // w_q^T  [N,K] tf32
__device__ float g_wkvT [2 * INNER * DIM];    // w_kv^T [N,K] tf32
__device__ float g_woutT[DIM * INNER];        // w_out^T[N,K] tf32

// ----------------------------------------------------------------------------
// Helpers
// ----------------------------------------------------------------------------
__device__ __forceinline__ uint32_t smem_u32(const void* p) {
    uint32_t a;
    asm("{ .reg .u64 t; cvta.to.shared.u64 t, %1; cvt.u32.u64 %0, t; }"
        : "=r"(a) : "l"(p));
    return a;
}
__device__ __forceinline__ float to_tf32(float x) {
    float r;
    asm("cvt.rna.tf32.f32 %0, %1;" : "=f"(r) : "f"(x));
    return r;
}

#define CP_ASYNC16(dst, src) \
    asm volatile("cp.async.cg.shared.global [%0], [%1], 16;" \
                 :: "r"(dst), "l"(src) : "memory")
#define CP_COMMIT() asm volatile("cp.async.commit_group;" ::: "memory")
#define CP_WAIT(n)  asm volatile("cp.async.wait_group %0;" :: "n"(n) : "memory")

// m16n8k8 tf32 mma: D += A*B (row.col), fp32 accum
__device__ __forceinline__ void mma_tf32(float* d, const uint32_t* a,
                                         const uint32_t* b) {
    asm volatile(
        "mma.sync.aligned.m16n8k8.row.col.f32.tf32.tf32.f32 "
        "{%0,%1,%2,%3}, {%4,%5,%6,%7}, {%8,%9}, {%0,%1,%2,%3};"
        : "+f"(d[0]), "+f"(d[1]), "+f"(d[2]), "+f"(d[3])
        : "r"(a[0]), "r"(a[1]), "r"(a[2]), "r"(a[3]), "r"(b[0]), "r"(b[1]));
}

// GEMM-tile swizzle (32-float rows, float4 XOR) — used by gemm_mma_kernel
__device__ __forceinline__ uint32_t lds_sw(const float* base, int row, int kf) {
    int idx = row * 32 + ((((kf >> 2) ^ (row & 7)) << 2) | (kf & 3));
    return __float_as_uint(base[idx]);
}

// Attention-tile swizzle: [row][64] tiles, addr = row*64 + (col ^ swz(row))
__device__ __forceinline__ int att_swz(int row) {
    return ((row & 3) << 3) | (row & 4);
}

// ----------------------------------------------------------------------------
// LayerNorm (tf32-rounded output)
// ----------------------------------------------------------------------------
__global__ void ln_kernel(const float* __restrict__ x,
                          const float* __restrict__ gamma,
                          const float* __restrict__ beta,
                          float* __restrict__ xn) {
    int row = blockIdx.x;
    int t   = threadIdx.x;
    const float* xr = x + (size_t)row * DIM;

    float4 v = *(const float4*)&xr[t * 4];
    float s  = v.x + v.y + v.z + v.w;
    float s2 = v.x*v.x + v.y*v.y + v.z*v.z + v.w*v.w;
    #pragma unroll
    for (int o = 16; o; o >>= 1) {
        s  += __shfl_xor_sync(0xffffffffu, s,  o);
        s2 += __shfl_xor_sync(0xffffffffu, s2, o);
    }
    __shared__ float sh1[8], sh2[8];
    int w = t >> 5, l = t & 31;
    if (l == 0) { sh1[w] = s; sh2[w] = s2; }
    __syncthreads();
    float ts = 0.f, ts2 = 0.f;
    #pragma unroll
    for (int i = 0; i < 8; i++) { ts += sh1[i]; ts2 += sh2[i]; }

    float mean = ts * (1.0f / DIM);
    float var  = ts2 * (1.0f / DIM) - mean * mean;
    float rstd = rsqrtf(var + 1e-5f);

    float4 g  = *(const float4*)&gamma[t * 4];
    float4 bb = *(const float4*)&beta[t * 4];
    float4 o;
    o.x = to_tf32((v.x - mean) * rstd * g.x + bb.x);
    o.y = to_tf32((v.y - mean) * rstd * g.y + bb.y);
    o.z = to_tf32((v.z - mean) * rstd * g.z + bb.z);
    o.w = to_tf32((v.w - mean) * rstd * g.w + bb.w);
    *(float4*)&xn[(size_t)row * DIM + t * 4] = o;
}

// ----------------------------------------------------------------------------
// Transpose + tf32 round: Wt[n,k] = tf32(W[k,n]).  W is [K, N].
// ----------------------------------------------------------------------------
__global__ void transpose_tf32_kernel(const float* __restrict__ W,
                                      float* __restrict__ Wt, int K, int N) {
    __shared__ float tile[32][33];
    int n0 = blockIdx.x * 32, k0 = blockIdx.y * 32;
    int tx = threadIdx.x, ty = threadIdx.y;
    #pragma unroll
    for (int i = ty; i < 32; i += 8)
        tile[i][tx] = W[(size_t)(k0 + i) * N + n0 + tx];
    __syncthreads();
    #pragma unroll
    for (int i = ty; i < 32; i += 8)
        Wt[(size_t)(n0 + i) * K + k0 + tx] = to_tf32(tile[tx][i]);
}

// ----------------------------------------------------------------------------
// tf32 mma.sync GEMM (unchanged from R4): C = A @ Bt^T (+bias)
// ----------------------------------------------------------------------------
#define GEMM_SMEM_FLOATS (4 * 4096)
#define CHUNKS (GK / 32)

__global__ __launch_bounds__(256)
void gemm_mma_kernel(const float* __restrict__ A,
                     const float* __restrict__ Bt,
                     float* __restrict__ C,
                     const float* __restrict__ bias,
                     int N) {
    extern __shared__ float smg[];
    float* sA[2] = { smg,          smg + 4096 };
    float* sB[2] = { smg + 8192,   smg + 12288 };
    uint32_t uA[2] = { smem_u32(sA[0]), smem_u32(sA[1]) };
    uint32_t uB[2] = { smem_u32(sB[0]), smem_u32(sB[1]) };

    int t    = threadIdx.x;
    int lane = t & 31;
    int wid  = t >> 5;
    int wm   = wid >> 1;
    int wn   = wid & 1;
    int gid  = lane >> 2;
    int tig  = lane & 3;
    int bm   = blockIdx.y * 128;
    int bn   = blockIdx.x * 128;

    const float* Ag = A  + (size_t)bm * GK;
    const float* Bg = Bt + (size_t)bn * GK;

    float acc[2][8][4];
    #pragma unroll
    for (int mt = 0; mt < 2; mt++)
        #pragma unroll
        for (int nt = 0; nt < 8; nt++)
            #pragma unroll
            for (int i = 0; i < 4; i++) acc[mt][nt][i] = 0.f;

    auto load_chunk = [&](int c, int s) {
        int k0 = c * 32;
        #pragma unroll
        for (int i = 0; i < 4; ++i) {
            int idx = t + i * 256;
            int row = idx >> 3, q = idx & 7;
            uint32_t d = uA[s] + (uint32_t)((row * 32 + ((q ^ (row & 7)) << 2)) * 4);
            CP_ASYNC16(d, Ag + (size_t)row * GK + k0 + q * 4);
        }
        #pragma unroll
        for (int i = 0; i < 4; ++i) {
            int idx = t + i * 256;
            int row = idx >> 3, q = idx & 7;
            uint32_t d = uB[s] + (uint32_t)((row * 32 + ((q ^ (row & 7)) << 2)) * 4);
            CP_ASYNC16(d, Bg + (size_t)row * GK + k0 + q * 4);
        }
        CP_COMMIT();
    };

    load_chunk(0, 0);
    load_chunk(1, 1);

    for (int c = 0; c < CHUNKS; ++c) {
        int s = c & 1;
        if (c == CHUNKS - 1) { CP_WAIT(0); } else { CP_WAIT(1); }
        __syncthreads();

        const float* a_s = sA[s];
        const float* b_s = sB[s];
        #pragma unroll
        for (int g = 0; g < 4; ++g) {
            uint32_t af[2][4];
            #pragma unroll
            for (int mt = 0; mt < 2; mt++) {
                int r = wm * 32 + mt * 16 + gid;
                af[mt][0] = lds_sw(a_s, r,     g * 8 + tig);
                af[mt][1] = lds_sw(a_s, r + 8, g * 8 + tig);
                af[mt][2] = lds_sw(a_s, r,     g * 8 + tig + 4);
                af[mt][3] = lds_sw(a_s, r + 8, g * 8 + tig + 4);
            }
            uint32_t bf[8][2];
            #pragma unroll
            for (int nt = 0; nt < 8; nt++) {
                int n = wn * 64 + nt * 8 + gid;
                bf[nt][0] = lds_sw(b_s, n, g * 8 + tig);
                bf[nt][1] = lds_sw(b_s, n, g * 8 + tig + 4);
            }
            #pragma unroll
            for (int mt = 0; mt < 2; mt++)
                #pragma unroll
                for (int nt = 0; nt < 8; nt++)
                    mma_tf32(acc[mt][nt], af[mt], bf[nt]);
        }
        __syncthreads();
        if (c + 2 < CHUNKS) load_chunk(c + 2, s);
    }

    #pragma unroll
    for (int mt = 0; mt < 2; mt++) {
        int r0 = bm + wm * 32 + mt * 16 + gid;
        #pragma unroll
        for (int nt = 0; nt < 8; nt++) {
            int cc = bn + wn * 64 + nt * 8 + tig * 2;
            float b0 = bias ? bias[cc]     : 0.f;
            float b1 = bias ? bias[cc + 1] : 0.f;
            *(float2*)&C[(size_t)r0 * N + cc] =
                make_float2(acc[mt][nt][0] + b0, acc[mt][nt][1] + b1);
            *(float2*)&C[(size_t)(r0 + 8) * N + cc] =
                make_float2(acc[mt][nt][2] + b0, acc[mt][nt][3] + b1);
        }
    }
}

// ----------------------------------------------------------------------------
// Flash attention on tensor cores (mma.sync tf32).
// CTA: 128 q-rows for one (b,h); 128 threads = 4 warps, each an m32 band.
// Key tiles of 64. All smem tiles use addr = row*64 + (col ^ att_swz(row)):
//   Qs [128][64] (Q*scale, tf32), Ks [64][64], Vs [64][64], Ps [128][64].
// All mma fragment reads conflict-free; V needs no transpose.
// ----------------------------------------------------------------------------
#define ATTN_SMEM_FLOATS (8192 + 4096 + 4096 + 8192)   // 96 KB

__global__ __launch_bounds__(128) void attn_mma_kernel(
    const float* __restrict__ q, const float* __restrict__ kv,
    float* __restrict__ o) {
    extern __shared__ float sma[];
    float* Qs = sma;              // [128][64]
    float* Ks = Qs + 8192;        // [64][64]
    float* Vs = Ks + 4096;        // [64][64]
    float* Ps = Vs + 4096;        // [128][64]

    int bh = blockIdx.y;
    int b  = bh >> 4, h = bh & 15;
    int q0 = blockIdx.x * 128;
    int t  = threadIdx.x;
    int lane = t & 31, w = t >> 5;
    int gid = lane >> 2, tig = lane & 3;
    int wm  = w * 32;
    int swzg = att_swz(gid);      // row&7 == gid for all Q/K/P fragment rows

    // Load Q tile once: scale + tf32 round, swizzled store
    #pragma unroll
    for (int i = 0; i < 16; i++) {
        int idx = i * 128 + t;
        int r = idx >> 4, qc = idx & 15;
        float4 v = *(const float4*)&q[((size_t)(b * SEQ + q0 + r)) * INNER
                                      + h * DHEAD + qc * 4];
        int c4 = qc ^ (att_swz(r) >> 2);
        float* p = &Qs[r * 64 + c4 * 4];
        p[0] = to_tf32(v.x * ATT_SCALE);
        p[1] = to_tf32(v.y * ATT_SCALE);
        p[2] = to_tf32(v.z * ATT_SCALE);
        p[3] = to_tf32(v.w * ATT_SCALE);
    }

    float m_[2][2], l_[2][2], oacc[2][8][4];
    #pragma unroll
    for (int mt = 0; mt < 2; mt++)
        #pragma unroll
        for (int hf = 0; hf < 2; hf++) { m_[mt][hf] = -1e30f; l_[mt][hf] = 0.f; }
    #pragma unroll
    for (int mt = 0; mt < 2; mt++)
        #pragma unroll
        for (int nt = 0; nt < 8; nt++)
            #pragma unroll
            for (int i = 0; i < 4; i++) oacc[mt][nt][i] = 0.f;

    for (int j0 = 0; j0 < SEQ; j0 += 64) {
        __syncthreads();   // prior iter's Vs/Ps reads complete
        // Load K and V tiles (64 rows x 64), tf32-rounded, swizzled
        #pragma unroll
        for (int i = 0; i < 8; i++) {
            int idx = i * 128 + t;
            int r = idx >> 4, qc = idx & 15;
            size_t gb = ((size_t)(b * SEQ + j0 + r)) * (2 * INNER)
                        + h * DHEAD + qc * 4;
            float4 kk = *(const float4*)&kv[gb];
            float4 vv = *(const float4*)&kv[gb + INNER];
            int c4 = qc ^ (att_swz(r) >> 2);
            float* pk = &Ks[r * 64 + c4 * 4];
            pk[0] = to_tf32(kk.x); pk[1] = to_tf32(kk.y);
            pk[2] = to_tf32(kk.z); pk[3] = to_tf32(kk.w);
            float* pv = &Vs[r * 64 + c4 * 4];
            pv[0] = to_tf32(vv.x); pv[1] = to_tf32(vv.y);
            pv[2] = to_tf32(vv.z); pv[3] = to_tf32(vv.w);
        }
        __syncthreads();

        // S = (Q*scale) @ K^T  : per warp m32 x n64, k = d = 64
        float sacc[2][8][4];
        #pragma unroll
        for (int mt = 0; mt < 2; mt++)
            #pragma unroll
            for (int nt = 0; nt < 8; nt++)
                #pragma unroll
                for (int i = 0; i < 4; i++) sacc[mt][nt][i] = 0.f;

        #pragma unroll
        for (int g = 0; g < 8; g++) {
            int kc = g * 8;
            uint32_t a[2][4];
            #pragma unroll
            for (int mt = 0; mt < 2; mt++) {
                int r0 = wm + mt * 16 + gid;
                a[mt][0] = __float_as_uint(Qs[r0 * 64       + ((kc + tig)     ^ swzg)]);
                a[mt][1] = __float_as_uint(Qs[(r0 + 8) * 64 + ((kc + tig)     ^ swzg)]);
                a[mt][2] = __float_as_uint(Qs[r0 * 64       + ((kc + tig + 4) ^ swzg)]);
                a[mt][3] = __float_as_uint(Qs[(r0 + 8) * 64 + ((kc + tig + 4) ^ swzg)]);
            }
            #pragma unroll
            for (int nt = 0; nt < 8; nt++) {
                int nr = nt * 8 + gid;
                uint32_t bf[2];
                bf[0] = __float_as_uint(Ks[nr * 64 + ((kc + tig)     ^ swzg)]);
                bf[1] = __float_as_uint(Ks[nr * 64 + ((kc + tig + 4) ^ swzg)]);
                mma_tf32(sacc[0][nt], a[0], bf);
                mma_tf32(sacc[1][nt], a[1], bf);
            }
        }

        // Online softmax in accumulator layout (quad lanes share rows)
        #pragma unroll
        for (int mt = 0; mt < 2; mt++) {
            #pragma unroll
            for (int hf = 0; hf < 2; hf++) {
                float mx = -1e30f;
                #pragma unroll
                for (int nt = 0; nt < 8; nt++) {
                    mx = fmaxf(mx, sacc[mt][nt][hf * 2]);
                    mx = fmaxf(mx, sacc[mt][nt][hf * 2 + 1]);
                }
                mx = fmaxf(mx, __shfl_xor_sync(0xffffffffu, mx, 1));
                mx = fmaxf(mx, __shfl_xor_sync(0xffffffffu, mx, 2));
                float mn = fmaxf(m_[mt][hf], mx);
                float alpha = __expf(m_[mt][hf] - mn);
                m_[mt][hf] = mn;
                float rs = 0.f;
                #pragma unroll
                for (int nt = 0; nt < 8; nt++) {
                    float p0 = to_tf32(__expf(sacc[mt][nt][hf * 2]     - mn));
                    float p1 = to_tf32(__expf(sacc[mt][nt][hf * 2 + 1] - mn));
                    sacc[mt][nt][hf * 2]     = p0;
                    sacc[mt][nt][hf * 2 + 1] = p1;
                    rs += p0 + p1;
                }
                rs += __shfl_xor_sync(0xffffffffu, rs, 1);
                rs += __shfl_xor_sync(0xffffffffu, rs, 2);
                l_[mt][hf] = l_[mt][hf] * alpha + rs;
                #pragma unroll
                for (int nt = 0; nt < 8; nt++) {
                    oacc[mt][nt][hf * 2]     *= alpha;
                    oacc[mt][nt][hf * 2 + 1] *= alpha;
                }
            }
        }

        // Stage P to smem (swizzled float2 stores)
        #pragma unroll
        for (int mt = 0; mt < 2; mt++) {
            int r0 = wm + mt * 16 + gid;
            #pragma unroll
            for (int nt = 0; nt < 8; nt++) {
                int c = (nt * 8 + tig * 2) ^ swzg;
                *(float2*)&Ps[r0 * 64 + c] =
                    make_float2(sacc[mt][nt][0], sacc[mt][nt][1]);
                *(float2*)&Ps[(r0 + 8) * 64 + c] =
                    make_float2(sacc[mt][nt][2], sacc[mt][nt][3]);
            }
        }
        __syncthreads();

        // O += P @ V : per warp m32 x n64(d), k = keys = 64
        #pragma unroll
        for (int g = 0; g < 8; g++) {
            int kc = g * 8;
            uint32_t a[2][4];
            #pragma unroll
            for (int mt = 0; mt < 2; mt++) {
                int r0 = wm + mt * 16 + gid;
                a[mt][0] = __float_as_uint(Ps[r0 * 64       + ((kc + tig)     ^ swzg)]);
                a[mt][1] = __float_as_uint(Ps[(r0 + 8) * 64 + ((kc + tig)     ^ swzg)]);
                a[mt][2] = __float_as_uint(Ps[r0 * 64       + ((kc + tig + 4) ^ swzg)]);
                a[mt][3] = __float_as_uint(Ps[(r0 + 8) * 64 + ((kc + tig + 4) ^ swzg)]);
            }
            int kr0 = (kc + tig) * 64;
            int kr1 = (kc + tig + 4) * 64;
            int sv0 = tig << 3, sv1 = (tig << 3) | 4;
            #pragma unroll
            for (int nt = 0; nt < 8; nt++) {
                int d0 = nt * 8 + gid;
                uint32_t bf[2];
                bf[0] = __float_as_uint(Vs[kr0 + (d0 ^ sv0)]);
                bf[1] = __float_as_uint(Vs[kr1 + (d0 ^ sv1)]);
                mma_tf32(oacc[0][nt], a[0], bf);
                mma_tf32(oacc[1][nt], a[1], bf);
            }
        }
    }

    // Epilogue: normalize, tf32-round, store
    #pragma unroll
    for (int mt = 0; mt < 2; mt++) {
        float inv0 = 1.f / l_[mt][0];
        float inv1 = 1.f / l_[mt][1];
        int r0 = q0 + wm + mt * 16 + gid;
        #pragma unroll
        for (int nt = 0; nt < 8; nt++) {
            int cc = h * DHEAD + nt * 8 + tig * 2;
            *(float2*)&o[((size_t)(b * SEQ + r0)) * INNER + cc] =
                make_float2(to_tf32(oacc[mt][nt][0] * inv0),
                            to_tf32(oacc[mt][nt][1] * inv0));
            *(float2*)&o[((size_t)(b * SEQ + r0 + 8)) * INNER + cc] =
                make_float2(to_tf32(oacc[mt][nt][2] * inv1),
                            to_tf32(oacc[mt][nt][3] * inv1));
        }
    }
}

// ----------------------------------------------------------------------------
// Launch
// ----------------------------------------------------------------------------
extern "C" void kernel_launch(void* const* d_in, const int* in_sizes, int n_in,
                              void* d_out, int out_size) {
    const float* x     = (const float*)d_in[0];
    const float* w_q   = (const float*)d_in[1];
    const float* w_kv  = (const float*)d_in[2];
    const float* w_out = (const float*)d_in[3];
    const float* b_out = (const float*)d_in[4];
    const float* gamma = (const float*)d_in[5];
    const float* beta  = (const float*)d_in[6];
    float* out = (float*)d_out;

    void *p_xn, *p_q, *p_kv, *p_attn, *p_wqT, *p_wkvT, *p_woutT;
    cudaGetSymbolAddress(&p_xn,    g_xn);
    cudaGetSymbolAddress(&p_q,     g_q);
    cudaGetSymbolAddress(&p_kv,    g_kv);
    cudaGetSymbolAddress(&p_attn,  g_attn);
    cudaGetSymbolAddress(&p_wqT,   g_wqT);
    cudaGetSymbolAddress(&p_wkvT,  g_wkvT);
    cudaGetSymbolAddress(&p_woutT, g_woutT);
    float* xn    = (float*)p_xn;
    float* qb    = (float*)p_q;
    float* kvb   = (float*)p_kv;
    float* attn  = (float*)p_attn;
    float* wqT   = (float*)p_wqT;
    float* wkvT  = (float*)p_wkvT;
    float* woutT = (float*)p_woutT;

    const int attn_smem = ATTN_SMEM_FLOATS * (int)sizeof(float);  // 98304
    const int gemm_smem = GEMM_SMEM_FLOATS * (int)sizeof(float);  // 65536
    cudaFuncSetAttribute(attn_mma_kernel,
                         cudaFuncAttributeMaxDynamicSharedMemorySize, attn_smem);
    cudaFuncSetAttribute(gemm_mma_kernel,
                         cudaFuncAttributeMaxDynamicSharedMemorySize, gemm_smem);

    // 0) Weight transposes (+ tf32 rounding)
    transpose_tf32_kernel<<<dim3(INNER/32,     DIM/32), dim3(32, 8)>>>(w_q,   wqT,   DIM, INNER);
    transpose_tf32_kernel<<<dim3(2*INNER/32,   DIM/32), dim3(32, 8)>>>(w_kv,  wkvT,  DIM, 2*INNER);
    transpose_tf32_kernel<<<dim3(DIM/32,     INNER/32), dim3(32, 8)>>>(w_out, woutT, INNER, DIM);

    // 1) LayerNorm (tf32-rounded output)
    ln_kernel<<<ROWS, 256>>>(x, gamma, beta, xn);

    // 2) Q and KV projections (mma.sync tf32)
    gemm_mma_kernel<<<dim3(INNER/128,   ROWS/128), 256, gemm_smem>>>(
        xn, wqT, qb, nullptr, INNER);
    gemm_mma_kernel<<<dim3(2*INNER/128, ROWS/128), 256, gemm_smem>>>(
        xn, wkvT, kvb, nullptr, 2*INNER);

    // 3) Flash attention (mma.sync tf32)
    attn_mma_kernel<<<dim3(SEQ/128, BATCH*HEADS), 128, attn_smem>>>(qb, kvb, attn);

    // 4) Output projection + bias (mma.sync tf32)
    gemm_mma_kernel<<<dim3(DIM/128, ROWS/128), 256, gemm_smem>>>(
        attn, woutT, out, b_out, DIM);
}